// round 15
// baseline (speedup 1.0000x reference)
#include <cuda_runtime.h>
#include <math.h>
#include <stdint.h>

// Problem constants
#define Bn   8
#define CIN  128
#define Hn   64
#define Wn   64
#define HWn  4096          // 64*64
#define COUT_MAIN 128

typedef unsigned long long ull;

// ---------------- device scratch (no allocations allowed) ----------------
__device__ float g_xnhwc[Bn * HWn * CIN];     // x transposed to NHWC (16 MB)
__device__ float g_offmask[Bn * HWn * 27];    // per-pixel: dy0,dx0,...,dy8,dx8, m0..m8
__device__ float g_wt_main[9 * CIN * 256];    // [k][c][2*co] duplicated pairs
__device__ float g_wt_om[9 * CIN * 64];       // [k][c][2*o]  duplicated pairs (27 pad 32)

// ---------------- f32x2 / async helpers ----------------
__device__ __forceinline__ ull ffma2(ull a, ull b, ull c) {
    ull d;
    asm("fma.rn.f32x2 %0, %1, %2, %3;" : "=l"(d) : "l"(a), "l"(b), "l"(c));
    return d;
}
__device__ __forceinline__ float f2lo(ull v) { return __uint_as_float((unsigned)v); }
__device__ __forceinline__ float f2hi(ull v) { return __uint_as_float((unsigned)(v >> 32)); }

__device__ __forceinline__ void cp16(uint32_t smem_dst, const void* gsrc) {
    asm volatile("cp.async.cg.shared.global [%0], [%1], 16;" :: "r"(smem_dst), "l"(gsrc));
}
__device__ __forceinline__ void cp_commit() {
    asm volatile("cp.async.commit_group;" ::: "memory");
}
__device__ __forceinline__ void cp_wait_all() {
    asm volatile("cp.async.wait_group 0;" ::: "memory");
}

// ---------------- kernel 0: fused NCHW->NHWC transpose + weight dup/relayout ----------------
__global__ void k_pre(const float* __restrict__ x,
                      const float* __restrict__ w_reg,
                      const float* __restrict__ w_off,
                      const float* __restrict__ w_mod) {
    __shared__ float s[128][65];
    int bid = blockIdx.x;
    int t = threadIdx.x;
    if (bid < 512) {
        int b = bid >> 6, h = bid & 63;
        const float* xp = x + (size_t)b * (CIN * HWn) + h * 64;
        for (int idx = t; idx < 8192; idx += 256) {
            int c = idx >> 6, w = idx & 63;
            s[c][w] = xp[c * HWn + w];
        }
        __syncthreads();
        float* op = g_xnhwc + (size_t)((b << 6) | h) * 64 * CIN;
        for (int idx = t; idx < 8192; idx += 256) {
            int w = idx >> 7, c = idx & 127;
            op[w * CIN + c] = s[c][w];
        }
    } else {
        int i = (bid - 512) * 256 + t;
        if (i < 9 * 128 * 256) {
            int co = (i & 255) >> 1, c = (i >> 8) & 127, k = i >> 15;
            g_wt_main[i] = w_reg[co * 1152 + c * 9 + k];
        } else {
            int j = i - 9 * 128 * 256;       // < 9*128*64 by grid sizing
            int o = (j & 63) >> 1, c = (j >> 6) & 127, k = j >> 13;
            float v = 0.f;
            if (o < 18)      v = w_off[o * 1152 + c * 9 + k];
            else if (o < 27) v = w_mod[(o - 18) * 1152 + c * 9 + k];
            g_wt_om[j] = v;
        }
    }
}

// corner gather (prologue): accumulate wgt * x[yi,xi,ch] into vr (32 ch per thread)
__device__ __forceinline__ void corner_acc(float4* vr, const float* xb, int gl,
                                           int yi, int xi, float wgt) {
    if (wgt != 0.f && (unsigned)yi < 64u && (unsigned)xi < 64u) {
        const float4* s4 = reinterpret_cast<const float4*>(xb + (size_t)((yi << 6) + xi) * CIN) + gl;
#pragma unroll
        for (int i = 0; i < 8; ++i) {
            float4 xv = __ldg(s4 + (i << 2));
            vr[i].x = fmaf(wgt, xv.x, vr[i].x);
            vr[i].y = fmaf(wgt, xv.y, vr[i].y);
            vr[i].z = fmaf(wgt, xv.z, vr[i].z);
            vr[i].w = fmaf(wgt, xv.w, vr[i].w);
        }
    }
}

// store vr (32 channels for pixel gp) into Vs with swizzle
__device__ __forceinline__ void sts_vr(float* vbuf, const float4* vr, int gp, int gl) {
    int px = gp ^ (gl << 3);
#pragma unroll
    for (int i = 0; i < 8; ++i) {
        int c0 = (gl + (i << 2)) << 2;
        vbuf[(c0 + 0) * 64 + px] = vr[i].x;
        vbuf[(c0 + 1) * 64 + px] = vr[i].y;
        vbuf[(c0 + 2) * 64 + px] = vr[i].z;
        vbuf[(c0 + 3) * 64 + px] = vr[i].w;
    }
}

// ---------------- main kernel ----------------
// Block = one (b,ho) row: 64 px x 128 co. px-pair f32x2 lanes, dup'd weights.
// Vs single-buffered (next tap's sample lives in regs until tap end);
// corner LDGs issued before each 16-ch GEMM slab, consumed after.
__global__ __launch_bounds__(256, 2)
void k_main(float* __restrict__ out) {
    extern __shared__ float sm[];
    float* Vs  = sm;                 // [128c][64px]            = 8192 floats
    float* Wsm = sm + 8192;          // [2][32c][256 dup]       = 16384 floats
    float* OM  = sm + 24576;         // [64*27]                 = 1728 floats

    const int bh = blockIdx.x;
    const int b  = bh >> 6;
    const int ho = bh & 63;
    const int t  = threadIdx.x;
    const int tx = t & 15;           // pixel group (4 px)
    const int ty = t >> 4;           // co group (8 co)
    const int gp = t >> 2;           // gather pixel
    const int gl = t & 3;            // gather lane
    const int px0 = tx << 2;

    const uint32_t ws_sm = (uint32_t)__cvta_generic_to_shared(Wsm);

    ull acc[8][2];
#pragma unroll
    for (int j = 0; j < 8; ++j) { acc[j][0] = 0ULL; acc[j][1] = 0ULL; }

    // load offsets/masks for this row
    {
        const float* src = g_offmask + (size_t)bh * 64 * 27;
        for (int i = t; i < 64 * 27; i += 256) OM[i] = src[i];
    }
    // prefetch dup'd weight chunk g=0 (tap0, ch 0..31): 32KB -> 128B/thread
    {
        uint32_t d = ws_sm + t * 128;
        const char* s = (const char*)g_wt_main + t * 128;
#pragma unroll
        for (int i = 0; i < 8; ++i) cp16(d + i * 16, s + i * 16);
        cp_commit();
    }
    __syncthreads();  // OM visible

    const float* xb = g_xnhwc + (size_t)b * HWn * CIN;
    const float* omp = &OM[gp * 27];

    float4 vr[8];
    // prologue: sample tap 0 -> Vs
    {
        float dy = omp[0], dx = omp[1], m = omp[18];
        float py = (float)(ho - 1) + dy;
        float px = (float)(gp - 1) + dx;
        float y0f = floorf(py), x0f = floorf(px);
        float wy = py - y0f, wx = px - x0f;
        int y0 = (int)y0f, x0 = (int)x0f;
#pragma unroll
        for (int i = 0; i < 8; ++i) vr[i] = make_float4(0.f, 0.f, 0.f, 0.f);
        corner_acc(vr, xb, gl, y0,     x0,     (1.f - wy) * (1.f - wx) * m);
        corner_acc(vr, xb, gl, y0,     x0 + 1, (1.f - wy) * wx * m);
        corner_acc(vr, xb, gl, y0 + 1, x0,     wy * (1.f - wx) * m);
        corner_acc(vr, xb, gl, y0 + 1, x0 + 1, wy * wx * m);
        sts_vr(Vs, vr, gp, gl);
    }

    int ny0 = 0, nx0 = 0;
    float w00 = 0.f, w01 = 0.f, w10 = 0.f, w11 = 0.f;

#pragma unroll 1
    for (int k = 0; k < 9; ++k) {
#pragma unroll 1
        for (int cc = 0; cc < 4; ++cc) {
            const int g = k * 4 + cc;
            cp_wait_all();
            __syncthreads();  // Ws chunk g ready; Vs/Ws buffer reuse safe

            if (g + 1 < 36) {
                uint32_t d = ws_sm + ((g + 1) & 1) * 32768 + t * 128;
                const char* s = (const char*)g_wt_main + (size_t)(g + 1) * 32768 + t * 128;
#pragma unroll
                for (int i = 0; i < 8; ++i) cp16(d + i * 16, s + i * 16);
                cp_commit();
            }

            // corner setup for tap k+1 (one corner per chunk)
            int yi = 0, xi = 0;
            float cw = 0.f;
            bool inb = false;
            if (k < 8) {
                if (cc == 0) {
                    const int kn = k + 1;
                    float dy = omp[2 * kn], dx = omp[2 * kn + 1], m = omp[18 + kn];
                    float py = (float)(ho + kn / 3 - 1) + dy;
                    float px = (float)(gp + kn % 3 - 1) + dx;
                    float y0f = floorf(py), x0f = floorf(px);
                    float wy = py - y0f, wx = px - x0f;
                    ny0 = (int)y0f; nx0 = (int)x0f;
                    w00 = (1.f - wy) * (1.f - wx) * m;
                    w01 = (1.f - wy) * wx * m;
                    w10 = wy * (1.f - wx) * m;
                    w11 = wy * wx * m;
#pragma unroll
                    for (int i = 0; i < 8; ++i) vr[i] = make_float4(0.f, 0.f, 0.f, 0.f);
                }
                yi = ny0 + (cc >> 1);
                xi = nx0 + (cc & 1);
                cw = (cc & 2) ? ((cc & 1) ? w11 : w10) : ((cc & 1) ? w01 : w00);
                inb = ((unsigned)yi < 64u) && ((unsigned)xi < 64u);
            }
            const float4* s4 = reinterpret_cast<const float4*>(
                xb + (size_t)(((yi & 63) << 6) + (xi & 63)) * CIN) + gl;

            const float* wsb = Wsm + (g & 1) * 8192 + (ty << 4);
            const float* vcb = Vs + (cc << 5) * 64;

#pragma unroll
            for (int hh = 0; hh < 2; ++hh) {
                // issue this corner's loads for channels hh*16..hh*16+15
                float4 lv0 = make_float4(0.f, 0.f, 0.f, 0.f), lv1 = lv0, lv2 = lv0, lv3 = lv0;
                if (k < 8 && inb) {
                    lv0 = __ldg(s4 + hh * 16 + 0);
                    lv1 = __ldg(s4 + hh * 16 + 4);
                    lv2 = __ldg(s4 + hh * 16 + 8);
                    lv3 = __ldg(s4 + hh * 16 + 12);
                }
                // GEMM slab: 16 channels
#pragma unroll 8
                for (int c2 = 0; c2 < 16; ++c2) {
                    const int c = hh * 16 + c2;
                    const int sw = ((c >> 2) & 3) << 3;
                    ulonglong2 vv = *reinterpret_cast<const ulonglong2*>(
                        vcb + c * 64 + (px0 ^ sw));
                    const ull* wp = reinterpret_cast<const ull*>(wsb + (c << 8));
#pragma unroll
                    for (int j = 0; j < 8; ++j) {
                        ull w = wp[j];
                        acc[j][0] = ffma2(w, vv.x, acc[j][0]);
                        acc[j][1] = ffma2(w, vv.y, acc[j][1]);
                    }
                }
                // consume corner loads (they landed under the GEMM)
                if (k < 8) {
                    float4* v0 = &vr[hh * 4];
                    v0[0].x = fmaf(cw, lv0.x, v0[0].x); v0[0].y = fmaf(cw, lv0.y, v0[0].y);
                    v0[0].z = fmaf(cw, lv0.z, v0[0].z); v0[0].w = fmaf(cw, lv0.w, v0[0].w);
                    v0[1].x = fmaf(cw, lv1.x, v0[1].x); v0[1].y = fmaf(cw, lv1.y, v0[1].y);
                    v0[1].z = fmaf(cw, lv1.z, v0[1].z); v0[1].w = fmaf(cw, lv1.w, v0[1].w);
                    v0[2].x = fmaf(cw, lv2.x, v0[2].x); v0[2].y = fmaf(cw, lv2.y, v0[2].y);
                    v0[2].z = fmaf(cw, lv2.z, v0[2].z); v0[2].w = fmaf(cw, lv2.w, v0[2].w);
                    v0[3].x = fmaf(cw, lv3.x, v0[3].x); v0[3].y = fmaf(cw, lv3.y, v0[3].y);
                    v0[3].z = fmaf(cw, lv3.z, v0[3].z); v0[3].w = fmaf(cw, lv3.w, v0[3].w);
                }
            }
        }
        if (k < 8) {
            __syncthreads();          // all warps done reading Vs for tap k
            sts_vr(Vs, vr, gp, gl);   // visible at next chunk barrier
        }
    }

    // epilogue -> NCHW: pixels are contiguous per co
    float* ob = out + (size_t)b * COUT_MAIN * HWn + (ho << 6) + px0;
#pragma unroll
    for (int j = 0; j < 8; ++j) {
        int co = ty * 8 + j;
        float4 r;
        r.x = f2lo(acc[j][0]); r.y = f2hi(acc[j][0]);
        r.z = f2lo(acc[j][1]); r.w = f2hi(acc[j][1]);
        *reinterpret_cast<float4*>(ob + (size_t)co * HWn) = r;
    }
}

// ---------------- aux kernel: plain 3x3 conv producing offsets+masks ----------------
// Block = 2 rows (128 px) x 32 outs. px-pair lanes + dup'd weights.
__global__ __launch_bounds__(256, 2)
void k_aux(const float* __restrict__ b_off, const float* __restrict__ b_mod) {
    extern __shared__ float sm[];
    float* Vs  = sm;               // [128c][128px] = 16384 floats
    float* Wsm = sm + 16384;       // [2][32c][64 dup] = 4096 floats

    const int blk = blockIdx.x;
    const int b   = blk >> 5;
    const int ho0 = (blk & 31) << 1;
    const int t   = threadIdx.x;
    const int tx  = t & 31;        // pixel group (4 px of 128)
    const int ty  = t >> 5;        // out group (4 outs)
    const int tp  = t >> 1;        // copy pixel
    const int th  = t & 1;         // copy half

    const uint32_t ws_sm = (uint32_t)__cvta_generic_to_shared(Wsm);

    ull acc[4][2];
#pragma unroll
    for (int j = 0; j < 4; ++j) { acc[j][0] = 0ULL; acc[j][1] = 0ULL; }

    // prefetch chunk 0: 8KB -> 32B/thread
    cp16(ws_sm + t * 32, (const char*)g_wt_om + t * 32);
    cp16(ws_sm + t * 32 + 16, (const char*)g_wt_om + t * 32 + 16);
    cp_commit();

    const float* xb = g_xnhwc + (size_t)b * HWn * CIN;

#pragma unroll 1
    for (int k = 0; k < 9; ++k) {
        const int kh = k / 3, kw = k % 3;
        __syncthreads();  // Vs reads of previous tap done

        // Phase A: guarded row copy (integer taps)
        {
            int row = tp >> 6, col = tp & 63;
            int ys = ho0 + row + kh - 1;
            int xs = col + kw - 1;
            bool val = ((unsigned)ys < 64u) && ((unsigned)xs < 64u);
            size_t base = val ? (size_t)((ys << 6) + xs) * CIN : 0;
            const float4* s4 = reinterpret_cast<const float4*>(xb + base) + th * 16;
#pragma unroll
            for (int j = 0; j < 16; ++j) {
                float4 xv = val ? __ldg(s4 + j) : make_float4(0.f, 0.f, 0.f, 0.f);
                int c0 = (th << 6) + (j << 2);
                Vs[(c0 + 0) * 128 + tp] = xv.x;
                Vs[(c0 + 1) * 128 + tp] = xv.y;
                Vs[(c0 + 2) * 128 + tp] = xv.z;
                Vs[(c0 + 3) * 128 + tp] = xv.w;
            }
        }

#pragma unroll 1
        for (int cc = 0; cc < 4; ++cc) {
            const int g = k * 4 + cc;
            cp_wait_all();
            __syncthreads();

            if (g + 1 < 36) {
                uint32_t d = ws_sm + ((g + 1) & 1) * 8192 + t * 32;
                const char* s = (const char*)g_wt_om + (size_t)(g + 1) * 8192 + t * 32;
                cp16(d, s); cp16(d + 16, s + 16);
                cp_commit();
            }

            const float* wsb = Wsm + (g & 1) * 2048 + (ty << 3);
            const float* vcb = Vs + (cc << 5) * 128 + (tx << 2);
#pragma unroll 8
            for (int c = 0; c < 32; ++c) {
                ulonglong2 vv = *reinterpret_cast<const ulonglong2*>(vcb + (c << 7));
                const ull* wp = reinterpret_cast<const ull*>(wsb + (c << 6));
#pragma unroll
                for (int j = 0; j < 4; ++j) {
                    ull w = wp[j];
                    acc[j][0] = ffma2(w, vv.x, acc[j][0]);
                    acc[j][1] = ffma2(w, vv.y, acc[j][1]);
                }
            }
        }
    }

    // epilogue: bias (+ 2*sigmoid for mask channels) -> g_offmask
#pragma unroll
    for (int j = 0; j < 4; ++j) {
        int o = (ty << 2) + j;
        if (o < 27) {
            float bias = (o < 18) ? b_off[o] : b_mod[o - 18];
            float vals[4];
            vals[0] = f2lo(acc[j][0]); vals[1] = f2hi(acc[j][0]);
            vals[2] = f2lo(acc[j][1]); vals[3] = f2hi(acc[j][1]);
#pragma unroll
            for (int i = 0; i < 4; ++i) {
                int p = (tx << 2) + i;
                int row = ho0 + (p >> 6), col = p & 63;
                float v = vals[i] + bias;
                if (o >= 18) v = 2.f / (1.f + expf(-v));
                g_offmask[(size_t)(((b << 6) + row) * 64 + col) * 27 + o] = v;
            }
        }
    }
}

// ---------------- launch ----------------
extern "C" void kernel_launch(void* const* d_in, const int* in_sizes, int n_in,
                              void* d_out, int out_size) {
    const float* x     = (const float*)d_in[0];
    const float* w_off = (const float*)d_in[1];
    const float* b_off = (const float*)d_in[2];
    const float* w_mod = (const float*)d_in[3];
    const float* b_mod = (const float*)d_in[4];
    const float* w_reg = (const float*)d_in[5];
    float* out = (float*)d_out;

    const int SMEM_MAIN = (8192 + 16384 + 1728) * 4;   // 105216 B
    const int SMEM_AUX  = (16384 + 4096) * 4;          //  81920 B
    cudaFuncSetAttribute(k_main, cudaFuncAttributeMaxDynamicSharedMemorySize, SMEM_MAIN);
    cudaFuncSetAttribute(k_aux,  cudaFuncAttributeMaxDynamicSharedMemorySize, SMEM_AUX);

    // 512 transpose blocks + (9*128*256 + 9*128*64)/256 = 1440 prep blocks
    k_pre<<<512 + 1440, 256>>>(x, w_reg, w_off, w_mod);
    k_aux<<<Bn * 32, 256, SMEM_AUX>>>(b_off, b_mod);
    k_main<<<Bn * Hn, 256, SMEM_MAIN>>>(out);
}

// round 16
// speedup vs baseline: 1.0006x; 1.0006x over previous
#include <cuda_runtime.h>
#include <math.h>
#include <stdint.h>

// Problem constants
#define Bn   8
#define CIN  128
#define Hn   64
#define Wn   64
#define HWn  4096          // 64*64
#define COUT_MAIN 128

typedef unsigned long long ull;

// ---------------- device scratch (no allocations allowed) ----------------
__device__ float g_xnhwc[Bn * HWn * CIN];     // x transposed to NHWC (16 MB)
__device__ float g_offmask[Bn * HWn * 27];    // per-pixel: dy0,dx0,...,dy8,dx8, m0..m8
__device__ float g_wt_main[9 * CIN * 256];    // [k][c][2*co] duplicated pairs
__device__ float g_wt_om[9 * CIN * 64];       // [k][c][2*o]  duplicated pairs (27 pad 32)

// ---------------- f32x2 / async helpers ----------------
__device__ __forceinline__ ull ffma2(ull a, ull b, ull c) {
    ull d;
    asm("fma.rn.f32x2 %0, %1, %2, %3;" : "=l"(d) : "l"(a), "l"(b), "l"(c));
    return d;
}
__device__ __forceinline__ float f2lo(ull v) { return __uint_as_float((unsigned)v); }
__device__ __forceinline__ float f2hi(ull v) { return __uint_as_float((unsigned)(v >> 32)); }

__device__ __forceinline__ void cp16(uint32_t smem_dst, const void* gsrc) {
    asm volatile("cp.async.cg.shared.global [%0], [%1], 16;" :: "r"(smem_dst), "l"(gsrc));
}
__device__ __forceinline__ void cp_commit() {
    asm volatile("cp.async.commit_group;" ::: "memory");
}
__device__ __forceinline__ void cp_wait_all() {
    asm volatile("cp.async.wait_group 0;" ::: "memory");
}

// ---------------- kernel 0: fused NCHW->NHWC transpose + weight dup/relayout ----------------
__global__ void k_pre(const float* __restrict__ x,
                      const float* __restrict__ w_reg,
                      const float* __restrict__ w_off,
                      const float* __restrict__ w_mod) {
    __shared__ float s[128][65];
    int bid = blockIdx.x;
    int t = threadIdx.x;
    if (bid < 512) {
        int b = bid >> 6, h = bid & 63;
        const float* xp = x + (size_t)b * (CIN * HWn) + h * 64;
        for (int idx = t; idx < 8192; idx += 256) {
            int c = idx >> 6, w = idx & 63;
            s[c][w] = xp[c * HWn + w];
        }
        __syncthreads();
        float* op = g_xnhwc + (size_t)((b << 6) | h) * 64 * CIN;
        for (int idx = t; idx < 8192; idx += 256) {
            int w = idx >> 7, c = idx & 127;
            op[w * CIN + c] = s[c][w];
        }
    } else {
        int i = (bid - 512) * 256 + t;
        if (i < 9 * 128 * 256) {
            int co = (i & 255) >> 1, c = (i >> 8) & 127, k = i >> 15;
            g_wt_main[i] = w_reg[co * 1152 + c * 9 + k];
        } else {
            int j = i - 9 * 128 * 256;       // < 9*128*64 by grid sizing
            int o = (j & 63) >> 1, c = (j >> 6) & 127, k = j >> 13;
            float v = 0.f;
            if (o < 18)      v = w_off[o * 1152 + c * 9 + k];
            else if (o < 27) v = w_mod[(o - 18) * 1152 + c * 9 + k];
            g_wt_om[j] = v;
        }
    }
}

// corner gather (prologue): accumulate wgt * x[yi,xi,ch] into vr (32 ch per thread)
__device__ __forceinline__ void corner_acc(float4* vr, const float* xb, int gl,
                                           int yi, int xi, float wgt) {
    if (wgt != 0.f && (unsigned)yi < 64u && (unsigned)xi < 64u) {
        const float4* s4 = reinterpret_cast<const float4*>(xb + (size_t)((yi << 6) + xi) * CIN) + gl;
#pragma unroll
        for (int i = 0; i < 8; ++i) {
            float4 xv = __ldg(s4 + (i << 2));
            vr[i].x = fmaf(wgt, xv.x, vr[i].x);
            vr[i].y = fmaf(wgt, xv.y, vr[i].y);
            vr[i].z = fmaf(wgt, xv.z, vr[i].z);
            vr[i].w = fmaf(wgt, xv.w, vr[i].w);
        }
    }
}

// store vr (32 channels for pixel gp) into Vs with swizzle
__device__ __forceinline__ void sts_vr(float* vbuf, const float4* vr, int gp, int gl) {
    int px = gp ^ (gl << 3);
#pragma unroll
    for (int i = 0; i < 8; ++i) {
        int c0 = (gl + (i << 2)) << 2;
        vbuf[(c0 + 0) * 64 + px] = vr[i].x;
        vbuf[(c0 + 1) * 64 + px] = vr[i].y;
        vbuf[(c0 + 2) * 64 + px] = vr[i].z;
        vbuf[(c0 + 3) * 64 + px] = vr[i].w;
    }
}

// ---------------- main kernel ----------------
// Block = one (b,ho) row: 64 px x 128 co. px-pair f32x2 lanes, dup'd weights.
// Vs single-buffered (next tap's sample lives in regs until tap end);
// corner LDGs issued before each 16-ch GEMM slab, consumed after.
__global__ __launch_bounds__(256, 2)
void k_main(float* __restrict__ out) {
    extern __shared__ float sm[];
    float* Vs  = sm;                 // [128c][64px]            = 8192 floats
    float* Wsm = sm + 8192;          // [2][32c][256 dup]       = 16384 floats
    float* OM  = sm + 24576;         // [64*27]                 = 1728 floats

    const int bh = blockIdx.x;
    const int b  = bh >> 6;
    const int ho = bh & 63;
    const int t  = threadIdx.x;
    const int tx = t & 15;           // pixel group (4 px)
    const int ty = t >> 4;           // co group (8 co)
    const int gp = t >> 2;           // gather pixel
    const int gl = t & 3;            // gather lane
    const int px0 = tx << 2;

    const uint32_t ws_sm = (uint32_t)__cvta_generic_to_shared(Wsm);

    ull acc[8][2];
#pragma unroll
    for (int j = 0; j < 8; ++j) { acc[j][0] = 0ULL; acc[j][1] = 0ULL; }

    // load offsets/masks for this row
    {
        const float* src = g_offmask + (size_t)bh * 64 * 27;
        for (int i = t; i < 64 * 27; i += 256) OM[i] = src[i];
    }
    // prefetch dup'd weight chunk g=0 (tap0, ch 0..31): 32KB -> 128B/thread
    {
        uint32_t d = ws_sm + t * 128;
        const char* s = (const char*)g_wt_main + t * 128;
#pragma unroll
        for (int i = 0; i < 8; ++i) cp16(d + i * 16, s + i * 16);
        cp_commit();
    }
    __syncthreads();  // OM visible

    const float* xb = g_xnhwc + (size_t)b * HWn * CIN;
    const float* omp = &OM[gp * 27];

    float4 vr[8];
    // prologue: sample tap 0 -> Vs
    {
        float dy = omp[0], dx = omp[1], m = omp[18];
        float py = (float)(ho - 1) + dy;
        float px = (float)(gp - 1) + dx;
        float y0f = floorf(py), x0f = floorf(px);
        float wy = py - y0f, wx = px - x0f;
        int y0 = (int)y0f, x0 = (int)x0f;
#pragma unroll
        for (int i = 0; i < 8; ++i) vr[i] = make_float4(0.f, 0.f, 0.f, 0.f);
        corner_acc(vr, xb, gl, y0,     x0,     (1.f - wy) * (1.f - wx) * m);
        corner_acc(vr, xb, gl, y0,     x0 + 1, (1.f - wy) * wx * m);
        corner_acc(vr, xb, gl, y0 + 1, x0,     wy * (1.f - wx) * m);
        corner_acc(vr, xb, gl, y0 + 1, x0 + 1, wy * wx * m);
        sts_vr(Vs, vr, gp, gl);
    }

    int ny0 = 0, nx0 = 0;
    float w00 = 0.f, w01 = 0.f, w10 = 0.f, w11 = 0.f;

#pragma unroll 1
    for (int k = 0; k < 9; ++k) {
#pragma unroll 1
        for (int cc = 0; cc < 4; ++cc) {
            const int g = k * 4 + cc;
            cp_wait_all();
            __syncthreads();  // Ws chunk g ready; Vs/Ws buffer reuse safe

            if (g + 1 < 36) {
                uint32_t d = ws_sm + ((g + 1) & 1) * 32768 + t * 128;
                const char* s = (const char*)g_wt_main + (size_t)(g + 1) * 32768 + t * 128;
#pragma unroll
                for (int i = 0; i < 8; ++i) cp16(d + i * 16, s + i * 16);
                cp_commit();
            }

            // corner setup for tap k+1 (one corner per chunk)
            int yi = 0, xi = 0;
            float cw = 0.f;
            bool inb = false;
            if (k < 8) {
                if (cc == 0) {
                    const int kn = k + 1;
                    float dy = omp[2 * kn], dx = omp[2 * kn + 1], m = omp[18 + kn];
                    float py = (float)(ho + kn / 3 - 1) + dy;
                    float px = (float)(gp + kn % 3 - 1) + dx;
                    float y0f = floorf(py), x0f = floorf(px);
                    float wy = py - y0f, wx = px - x0f;
                    ny0 = (int)y0f; nx0 = (int)x0f;
                    w00 = (1.f - wy) * (1.f - wx) * m;
                    w01 = (1.f - wy) * wx * m;
                    w10 = wy * (1.f - wx) * m;
                    w11 = wy * wx * m;
#pragma unroll
                    for (int i = 0; i < 8; ++i) vr[i] = make_float4(0.f, 0.f, 0.f, 0.f);
                }
                yi = ny0 + (cc >> 1);
                xi = nx0 + (cc & 1);
                cw = (cc & 2) ? ((cc & 1) ? w11 : w10) : ((cc & 1) ? w01 : w00);
                inb = ((unsigned)yi < 64u) && ((unsigned)xi < 64u);
            }
            const float4* s4 = reinterpret_cast<const float4*>(
                xb + (size_t)(((yi & 63) << 6) + (xi & 63)) * CIN) + gl;

            const float* wsb = Wsm + (g & 1) * 8192 + (ty << 4);
            const float* vcb = Vs + (cc << 5) * 64;

#pragma unroll
            for (int hh = 0; hh < 2; ++hh) {
                // issue this corner's loads for channels hh*16..hh*16+15
                float4 lv0 = make_float4(0.f, 0.f, 0.f, 0.f), lv1 = lv0, lv2 = lv0, lv3 = lv0;
                if (k < 8 && inb) {
                    lv0 = __ldg(s4 + hh * 16 + 0);
                    lv1 = __ldg(s4 + hh * 16 + 4);
                    lv2 = __ldg(s4 + hh * 16 + 8);
                    lv3 = __ldg(s4 + hh * 16 + 12);
                }
                // GEMM slab: 16 channels
#pragma unroll 8
                for (int c2 = 0; c2 < 16; ++c2) {
                    const int c = hh * 16 + c2;
                    const int sw = ((c >> 2) & 3) << 3;
                    ulonglong2 vv = *reinterpret_cast<const ulonglong2*>(
                        vcb + c * 64 + (px0 ^ sw));
                    const ull* wp = reinterpret_cast<const ull*>(wsb + (c << 8));
#pragma unroll
                    for (int j = 0; j < 8; ++j) {
                        ull w = wp[j];
                        acc[j][0] = ffma2(w, vv.x, acc[j][0]);
                        acc[j][1] = ffma2(w, vv.y, acc[j][1]);
                    }
                }
                // consume corner loads (they landed under the GEMM)
                if (k < 8) {
                    float4* v0 = &vr[hh * 4];
                    v0[0].x = fmaf(cw, lv0.x, v0[0].x); v0[0].y = fmaf(cw, lv0.y, v0[0].y);
                    v0[0].z = fmaf(cw, lv0.z, v0[0].z); v0[0].w = fmaf(cw, lv0.w, v0[0].w);
                    v0[1].x = fmaf(cw, lv1.x, v0[1].x); v0[1].y = fmaf(cw, lv1.y, v0[1].y);
                    v0[1].z = fmaf(cw, lv1.z, v0[1].z); v0[1].w = fmaf(cw, lv1.w, v0[1].w);
                    v0[2].x = fmaf(cw, lv2.x, v0[2].x); v0[2].y = fmaf(cw, lv2.y, v0[2].y);
                    v0[2].z = fmaf(cw, lv2.z, v0[2].z); v0[2].w = fmaf(cw, lv2.w, v0[2].w);
                    v0[3].x = fmaf(cw, lv3.x, v0[3].x); v0[3].y = fmaf(cw, lv3.y, v0[3].y);
                    v0[3].z = fmaf(cw, lv3.z, v0[3].z); v0[3].w = fmaf(cw, lv3.w, v0[3].w);
                }
            }
        }
        if (k < 8) {
            __syncthreads();          // all warps done reading Vs for tap k
            sts_vr(Vs, vr, gp, gl);   // visible at next chunk barrier
        }
    }

    // epilogue -> NCHW: pixels are contiguous per co
    float* ob = out + (size_t)b * COUT_MAIN * HWn + (ho << 6) + px0;
#pragma unroll
    for (int j = 0; j < 8; ++j) {
        int co = ty * 8 + j;
        float4 r;
        r.x = f2lo(acc[j][0]); r.y = f2hi(acc[j][0]);
        r.z = f2lo(acc[j][1]); r.w = f2hi(acc[j][1]);
        *reinterpret_cast<float4*>(ob + (size_t)co * HWn) = r;
    }
}

// ---------------- aux kernel: plain 3x3 conv producing offsets+masks ----------------
// Block = 2 rows (128 px) x 32 outs. px-pair lanes + dup'd weights.
__global__ __launch_bounds__(256, 2)
void k_aux(const float* __restrict__ b_off, const float* __restrict__ b_mod) {
    extern __shared__ float sm[];
    float* Vs  = sm;               // [128c][128px] = 16384 floats
    float* Wsm = sm + 16384;       // [2][32c][64 dup] = 4096 floats

    const int blk = blockIdx.x;
    const int b   = blk >> 5;
    const int ho0 = (blk & 31) << 1;
    const int t   = threadIdx.x;
    const int tx  = t & 31;        // pixel group (4 px of 128)
    const int ty  = t >> 5;        // out group (4 outs)
    const int tp  = t >> 1;        // copy pixel
    const int th  = t & 1;         // copy half

    const uint32_t ws_sm = (uint32_t)__cvta_generic_to_shared(Wsm);

    ull acc[4][2];
#pragma unroll
    for (int j = 0; j < 4; ++j) { acc[j][0] = 0ULL; acc[j][1] = 0ULL; }

    // prefetch chunk 0: 8KB -> 32B/thread
    cp16(ws_sm + t * 32, (const char*)g_wt_om + t * 32);
    cp16(ws_sm + t * 32 + 16, (const char*)g_wt_om + t * 32 + 16);
    cp_commit();

    const float* xb = g_xnhwc + (size_t)b * HWn * CIN;

#pragma unroll 1
    for (int k = 0; k < 9; ++k) {
        const int kh = k / 3, kw = k % 3;
        __syncthreads();  // Vs reads of previous tap done

        // Phase A: guarded row copy (integer taps)
        {
            int row = tp >> 6, col = tp & 63;
            int ys = ho0 + row + kh - 1;
            int xs = col + kw - 1;
            bool val = ((unsigned)ys < 64u) && ((unsigned)xs < 64u);
            size_t base = val ? (size_t)((ys << 6) + xs) * CIN : 0;
            const float4* s4 = reinterpret_cast<const float4*>(xb + base) + th * 16;
#pragma unroll
            for (int j = 0; j < 16; ++j) {
                float4 xv = val ? __ldg(s4 + j) : make_float4(0.f, 0.f, 0.f, 0.f);
                int c0 = (th << 6) + (j << 2);
                Vs[(c0 + 0) * 128 + tp] = xv.x;
                Vs[(c0 + 1) * 128 + tp] = xv.y;
                Vs[(c0 + 2) * 128 + tp] = xv.z;
                Vs[(c0 + 3) * 128 + tp] = xv.w;
            }
        }

#pragma unroll 1
        for (int cc = 0; cc < 4; ++cc) {
            const int g = k * 4 + cc;
            cp_wait_all();
            __syncthreads();

            if (g + 1 < 36) {
                uint32_t d = ws_sm + ((g + 1) & 1) * 8192 + t * 32;
                const char* s = (const char*)g_wt_om + (size_t)(g + 1) * 8192 + t * 32;
                cp16(d, s); cp16(d + 16, s + 16);
                cp_commit();
            }

            const float* wsb = Wsm + (g & 1) * 2048 + (ty << 3);
            const float* vcb = Vs + (cc << 5) * 128 + (tx << 2);
#pragma unroll 8
            for (int c = 0; c < 32; ++c) {
                ulonglong2 vv = *reinterpret_cast<const ulonglong2*>(vcb + (c << 7));
                const ull* wp = reinterpret_cast<const ull*>(wsb + (c << 6));
#pragma unroll
                for (int j = 0; j < 4; ++j) {
                    ull w = wp[j];
                    acc[j][0] = ffma2(w, vv.x, acc[j][0]);
                    acc[j][1] = ffma2(w, vv.y, acc[j][1]);
                }
            }
        }
    }

    // epilogue: bias (+ 2*sigmoid for mask channels) -> g_offmask
#pragma unroll
    for (int j = 0; j < 4; ++j) {
        int o = (ty << 2) + j;
        if (o < 27) {
            float bias = (o < 18) ? b_off[o] : b_mod[o - 18];
            float vals[4];
            vals[0] = f2lo(acc[j][0]); vals[1] = f2hi(acc[j][0]);
            vals[2] = f2lo(acc[j][1]); vals[3] = f2hi(acc[j][1]);
#pragma unroll
            for (int i = 0; i < 4; ++i) {
                int p = (tx << 2) + i;
                int row = ho0 + (p >> 6), col = p & 63;
                float v = vals[i] + bias;
                if (o >= 18) v = 2.f / (1.f + expf(-v));
                g_offmask[(size_t)(((b << 6) + row) * 64 + col) * 27 + o] = v;
            }
        }
    }
}

// ---------------- launch ----------------
extern "C" void kernel_launch(void* const* d_in, const int* in_sizes, int n_in,
                              void* d_out, int out_size) {
    const float* x     = (const float*)d_in[0];
    const float* w_off = (const float*)d_in[1];
    const float* b_off = (const float*)d_in[2];
    const float* w_mod = (const float*)d_in[3];
    const float* b_mod = (const float*)d_in[4];
    const float* w_reg = (const float*)d_in[5];
    float* out = (float*)d_out;

    const int SMEM_MAIN = (8192 + 16384 + 1728) * 4;   // 105216 B
    const int SMEM_AUX  = (16384 + 4096) * 4;          //  81920 B
    cudaFuncSetAttribute(k_main, cudaFuncAttributeMaxDynamicSharedMemorySize, SMEM_MAIN);
    cudaFuncSetAttribute(k_aux,  cudaFuncAttributeMaxDynamicSharedMemorySize, SMEM_AUX);

    // 512 transpose blocks + (9*128*256 + 9*128*64)/256 = 1440 prep blocks
    k_pre<<<512 + 1440, 256>>>(x, w_reg, w_off, w_mod);
    k_aux<<<Bn * 32, 256, SMEM_AUX>>>(b_off, b_mod);
    k_main<<<Bn * Hn, 256, SMEM_MAIN>>>(out);
}